// round 10
// baseline (speedup 1.0000x reference)
#include <cuda_runtime.h>
#include <cuda_bf16.h>

#define DIM    2048
#define BATCH  32
#define KTOP   256
#define LOG2E  1.44269504f

// sorted chunk keys (monotonic u32, value-only) [b][chunk][256]
__device__ __align__(16) unsigned int g_key[BATCH * DIM];
// inclusive prefix sums of values in chunk-sorted order, same layout
__device__ __align__(16) float g_pref[BATCH * DIM];
// Bsum * log2e, original index order
__device__ __align__(16) float g_bsum[BATCH * DIM];
// top-256 by global rank: slot r-1792 holds (s*log2e, B*log2e) of rank-r element
__device__ __align__(16) float g_topv[BATCH * KTOP];
__device__ __align__(16) float g_topB[BATCH * KTOP];

__device__ __forceinline__ float ex2f(float x) {
    float r; asm("ex2.approx.ftz.f32 %0, %1;" : "=f"(r) : "f"(x)); return r;
}
__device__ __forceinline__ float rcpf(float x) {
    float r; asm("rcp.approx.f32 %0, %1;" : "=f"(r) : "f"(x)); return r;
}
__device__ __forceinline__ unsigned int monokey(float f) {
    unsigned int u = __float_as_uint(f);
    return u ^ (((unsigned int)((int)u >> 31)) | 0x80000000u);
}
__device__ __forceinline__ float unmono(unsigned int u) {
    return __uint_as_float(u ^ ((~((unsigned int)((int)u >> 31))) | 0x80000000u));
}
__device__ __forceinline__ unsigned int cmpex32(unsigned int v, int t, int j, bool d) {
    unsigned int o = __shfl_xor_sync(0xffffffffu, v, j);
    bool takeMin = (((t & j) == 0) == d);
    return (takeMin ? (o < v) : (o > v)) ? o : v;
}

// ---------------------------------------------------------------------------
// Kernel A: sort one 256-element chunk of TWO batch rows per block, 32-bit
// value-only keys (no payload: ranks handle ties analytically).
// Grid (8 chunks, 16 row-pairs) x 256. Outputs sorted keys + inclusive
// value-prefix sums per chunk.
// ---------------------------------------------------------------------------
__global__ __launch_bounds__(256) void chunk_sort_kernel(const float* __restrict__ scores) {
    __shared__ unsigned int buf0[256], buf1[256];
    __shared__ float wtot[2][8];
    const int chunk = blockIdx.x, bp = blockIdx.y, t = threadIdx.x;
    const int lane = t & 31, w = t >> 5;
    const int b0 = bp * 2, b1 = b0 + 1;
    const int gi = (chunk << 8) + t;

    unsigned int K0 = monokey(scores[(b0 << 11) + gi]);
    unsigned int K1 = monokey(scores[(b1 << 11) + gi]);

    // stages k=2..32: intra-warp shfl, two independent networks interleaved
    #pragma unroll
    for (int k = 2; k <= 32; k <<= 1) {
        const bool d = ((t & k) == 0);
        #pragma unroll
        for (int j = k >> 1; j > 0; j >>= 1) {
            K0 = cmpex32(K0, t, j, d);
            K1 = cmpex32(K1, t, j, d);
        }
    }
    // stages k=64..256: j>=32 via smem, rest shfl
    #pragma unroll
    for (int k = 64; k <= 256; k <<= 1) {
        const bool d = ((t & k) == 0);
        #pragma unroll
        for (int j = k >> 1; j > 0; j >>= 1) {
            if (j >= 32) {
                __syncthreads();
                buf0[t] = K0; buf1[t] = K1;
                __syncthreads();
                unsigned int o0 = buf0[t ^ j];
                unsigned int o1 = buf1[t ^ j];
                bool takeMin = (((t & j) == 0) == d);
                K0 = (takeMin ? (o0 < K0) : (o0 > K0)) ? o0 : K0;
                K1 = (takeMin ? (o1 < K1) : (o1 > K1)) ? o1 : K1;
            } else {
                K0 = cmpex32(K0, t, j, d);
                K1 = cmpex32(K1, t, j, d);
            }
        }
    }

    const float v0 = unmono(K0);
    const float v1 = unmono(K1);

    // two interleaved inclusive block scans
    float x0 = v0, x1 = v1;
    #pragma unroll
    for (int o = 1; o < 32; o <<= 1) {
        float y0 = __shfl_up_sync(0xffffffffu, x0, o);
        float y1 = __shfl_up_sync(0xffffffffu, x1, o);
        if (lane >= o) { x0 += y0; x1 += y1; }
    }
    if (lane == 31) { wtot[0][w] = x0; wtot[1][w] = x1; }
    __syncthreads();
    float off0 = 0.f, off1 = 0.f;
    #pragma unroll
    for (int ww = 0; ww < 7; ww++)
        if (ww < w) { off0 += wtot[0][ww]; off1 += wtot[1][ww]; }

    g_key[(b0 << 11) + gi]  = K0;
    g_key[(b1 << 11) + gi]  = K1;
    g_pref[(b0 << 11) + gi] = off0 + x0;
    g_pref[(b1 << 11) + gi] = off1 + x1;
}

// ---------------------------------------------------------------------------
// Kernel B: for each element (ORIGINAL order -> coalesced stores), rank and
// smaller-sum via 16 interleaved branchless binary searches (lower bound with
// K and with K+1 => strict-less count r and equal count d) over the 8 sorted
// chunks staged in smem.  B_i = s_i*(2r-n) + T - 2P.  Elements whose rank
// range [r, r+d) intersects [1792,2048) fill those top slots (tied elements
// write identical data).
// ---------------------------------------------------------------------------
__global__ __launch_bounds__(256) void bsum_search_kernel(const float* __restrict__ scores) {
    __shared__ __align__(16) unsigned int skey[DIM];   // 8 KB
    __shared__ __align__(16) float spref[DIM];         // 8 KB
    const int ic = blockIdx.x, b = blockIdx.y, t = threadIdx.x;

    {   // stage the whole row's sorted chunks
        const uint4* gk4 = (const uint4*)(g_key + (b << 11));
        uint4* sk4 = (uint4*)skey;
        #pragma unroll
        for (int c = 0; c < 2; c++) sk4[t + c * 256] = gk4[t + c * 256];
        const float4* gp4 = (const float4*)(g_pref + (b << 11));
        float4* sp4 = (float4*)spref;
        #pragma unroll
        for (int c = 0; c < 2; c++) sp4[t + c * 256] = gp4[t + c * 256];
    }
    __syncthreads();

    const int i = (ic << 8) + t;
    const float s = scores[(b << 11) + i];
    const unsigned int K  = monokey(s);
    const unsigned int Ku = K + 1;          // upper bound = lower_bound(K+1)

    // 16 interleaved branchless lower-bound searches
    int pl[8], pu[8];
    #pragma unroll
    for (int c = 0; c < 8; c++) { pl[c] = 0; pu[c] = 0; }
    #pragma unroll
    for (int st = 128; st >= 1; st >>= 1) {
        #pragma unroll
        for (int c = 0; c < 8; c++) {
            if (skey[(c << 8) + pl[c] + st - 1] < K)  pl[c] += st;
            if (skey[(c << 8) + pu[c] + st - 1] < Ku) pu[c] += st;
        }
    }
    #pragma unroll
    for (int c = 0; c < 8; c++) {
        if (skey[(c << 8) + pl[c]] < K)  pl[c]++;
        if (skey[(c << 8) + pu[c]] < Ku) pu[c]++;
    }

    int r = 0, ru = 0;
    float P = 0.f, T = 0.f;
    #pragma unroll
    for (int c = 0; c < 8; c++) {
        r  += pl[c];
        ru += pu[c];
        if (pl[c] > 0) P += spref[(c << 8) + pl[c] - 1];
        T += spref[(c << 8) + 255];
    }

    const float B = fmaf(s, (float)(2 * r - DIM), T - 2.f * P);
    g_bsum[(b << 11) + i] = B * LOG2E;

    if (ru > DIM - KTOP) {                 // rank range [r, ru) hits top-256
        int lo = r > (DIM - KTOP) ? r : (DIM - KTOP);
        for (int rr = lo; rr < ru; rr++) { // almost always 1 iteration
            g_topv[(b << 8) + rr - (DIM - KTOP)] = s * LOG2E;
            g_topB[(b << 8) + rr - (DIM - KTOP)] = B * LOG2E;
        }
    }
}

// ---------------------------------------------------------------------------
// Kernel C: fused softmax writer, KPB=16, k's processed in pairs. M is
// analytic (rank 2047-k element => slot 255-k): one barrier per 2 k's,
// double-buffered reduction slots. Grid (16 kg, 32 b) x 256 threads.
// ---------------------------------------------------------------------------
__global__ __launch_bounds__(256) void softmax_kernel(const float* __restrict__ scores,
                                                      float* __restrict__ out) {
    __shared__ float redS[32];                 // 2 buffers x (8+8) warp sums
    const int kg = blockIdx.x, b = blockIdx.y, t = threadIdx.x;
    const int lane = t & 31, w = t >> 5;

    const float4* sc4 = (const float4*)(scores + (b << 11));
    const float4* bs4 = (const float4*)(g_bsum + (b << 11));
    float4 a0 = sc4[t], a1 = sc4[t + 256];
    const float4 c0 = bs4[t], c1 = bs4[t + 256];
    a0.x *= LOG2E; a0.y *= LOG2E; a0.z *= LOG2E; a0.w *= LOG2E;
    a1.x *= LOG2E; a1.y *= LOG2E; a1.z *= LOG2E; a1.w *= LOG2E;

    #pragma unroll
    for (int kp = 0; kp < 8; kp++) {
        const int k0 = (kg << 4) + 2 * kp;
        const int k1 = k0 + 1;
        const float scal0 = (float)(DIM - 1 - 2 * k0);
        const float scal1 = (float)(DIM - 1 - 2 * k1);
        const float M0 = fmaf(scal0, __ldg(&g_topv[(b << 8) + 255 - k0]),
                              -__ldg(&g_topB[(b << 8) + 255 - k0]));
        const float M1 = fmaf(scal1, __ldg(&g_topv[(b << 8) + 255 - k1]),
                              -__ldg(&g_topB[(b << 8) + 255 - k1]));

        float e0[8], e1[8];
        e0[0] = ex2f(fmaf(a0.x, scal0, -c0.x) - M0);
        e0[1] = ex2f(fmaf(a0.y, scal0, -c0.y) - M0);
        e0[2] = ex2f(fmaf(a0.z, scal0, -c0.z) - M0);
        e0[3] = ex2f(fmaf(a0.w, scal0, -c0.w) - M0);
        e0[4] = ex2f(fmaf(a1.x, scal0, -c1.x) - M0);
        e0[5] = ex2f(fmaf(a1.y, scal0, -c1.y) - M0);
        e0[6] = ex2f(fmaf(a1.z, scal0, -c1.z) - M0);
        e0[7] = ex2f(fmaf(a1.w, scal0, -c1.w) - M0);
        e1[0] = ex2f(fmaf(a0.x, scal1, -c0.x) - M1);
        e1[1] = ex2f(fmaf(a0.y, scal1, -c0.y) - M1);
        e1[2] = ex2f(fmaf(a0.z, scal1, -c0.z) - M1);
        e1[3] = ex2f(fmaf(a0.w, scal1, -c0.w) - M1);
        e1[4] = ex2f(fmaf(a1.x, scal1, -c1.x) - M1);
        e1[5] = ex2f(fmaf(a1.y, scal1, -c1.y) - M1);
        e1[6] = ex2f(fmaf(a1.z, scal1, -c1.z) - M1);
        e1[7] = ex2f(fmaf(a1.w, scal1, -c1.w) - M1);

        float s0 = ((e0[0] + e0[1]) + (e0[2] + e0[3])) + ((e0[4] + e0[5]) + (e0[6] + e0[7]));
        float s1 = ((e1[0] + e1[1]) + (e1[2] + e1[3])) + ((e1[4] + e1[5]) + (e1[6] + e1[7]));
        #pragma unroll
        for (int o = 16; o; o >>= 1) {       // two independent chains overlap
            s0 += __shfl_xor_sync(0xffffffffu, s0, o);
            s1 += __shfl_xor_sync(0xffffffffu, s1, o);
        }
        const int p = (kp & 1) << 4;
        if (lane == 0) { redS[p + w] = s0; redS[p + 8 + w] = s1; }
        __syncthreads();                     // one barrier per 2 k's
        float S0 = redS[p + (lane & 7)];
        float S1 = redS[p + 8 + (lane & 7)];
        #pragma unroll
        for (int o = 4; o; o >>= 1) {
            S0 += __shfl_xor_sync(0xffffffffu, S0, o);
            S1 += __shfl_xor_sync(0xffffffffu, S1, o);
        }

        const float i0 = rcpf(S0);
        const float i1 = rcpf(S1);
        float4* o0p = (float4*)(out + ((size_t)((b << 8) + k0) << 11));
        float4* o1p = (float4*)(out + ((size_t)((b << 8) + k1) << 11));
        o0p[t]       = make_float4(e0[0] * i0, e0[1] * i0, e0[2] * i0, e0[3] * i0);
        o0p[t + 256] = make_float4(e0[4] * i0, e0[5] * i0, e0[6] * i0, e0[7] * i0);
        o1p[t]       = make_float4(e1[0] * i1, e1[1] * i1, e1[2] * i1, e1[3] * i1);
        o1p[t + 256] = make_float4(e1[4] * i1, e1[5] * i1, e1[6] * i1, e1[7] * i1);
    }
}

extern "C" void kernel_launch(void* const* d_in, const int* in_sizes, int n_in,
                              void* d_out, int out_size) {
    const float* scores = (const float*)d_in[0];
    float* out = (float*)d_out;

    chunk_sort_kernel<<<dim3(DIM / 256, BATCH / 2), 256>>>(scores);
    bsum_search_kernel<<<dim3(DIM / 256, BATCH), 256>>>(scores);
    softmax_kernel<<<dim3(KTOP / 16, BATCH), 256>>>(scores, out);
}

// round 11
// speedup vs baseline: 1.1772x; 1.1772x over previous
#include <cuda_runtime.h>
#include <cuda_bf16.h>

#define DIM    2048
#define BATCH  32
#define KTOP   256
#define LOG2E  1.44269504f

// sorted chunk keys (monotonic u32, value-only) [b][chunk][256]
__device__ __align__(16) unsigned int g_key[BATCH * DIM];
// inclusive prefix sums of values in chunk-sorted order, same layout
__device__ __align__(16) float g_pref[BATCH * DIM];
// Bsum * log2e, original index order
__device__ __align__(16) float g_bsum[BATCH * DIM];
// top-256 by global rank: slot r-1792 holds (s*log2e, B*log2e) of rank-r element
__device__ __align__(16) float g_topv[BATCH * KTOP];
__device__ __align__(16) float g_topB[BATCH * KTOP];

__device__ __forceinline__ float ex2f(float x) {
    float r; asm("ex2.approx.ftz.f32 %0, %1;" : "=f"(r) : "f"(x)); return r;
}
__device__ __forceinline__ float rcpf(float x) {
    float r; asm("rcp.approx.f32 %0, %1;" : "=f"(r) : "f"(x)); return r;
}
__device__ __forceinline__ unsigned int monokey(float f) {
    unsigned int u = __float_as_uint(f);
    return u ^ (((unsigned int)((int)u >> 31)) | 0x80000000u);
}
__device__ __forceinline__ float unmono(unsigned int u) {
    return __uint_as_float(u ^ ((~((unsigned int)((int)u >> 31))) | 0x80000000u));
}

// ---------------------------------------------------------------------------
// Kernel A: chunk sort by RANK COUNTING (no compare-exchange network, no
// dependency chain — pure ALU/LDS throughput). Grid (8 chunks, 32 b) x 256.
// Each thread counts strict-less among its 256-chunk (vectorized LDS.128),
// resolves ties via a smem atomic per base rank (tied elements carry equal
// values, so output is tie-order invariant => deterministic), scatters to
// sorted order, then computes inclusive value-prefix sums.
// ---------------------------------------------------------------------------
__global__ __launch_bounds__(256) void chunk_rank_kernel(const float* __restrict__ scores) {
    __shared__ __align__(16) unsigned int sk[256];
    __shared__ unsigned int ssort[256];
    __shared__ int ctr[256];
    __shared__ float wtot[8];
    const int chunk = blockIdx.x, b = blockIdx.y, t = threadIdx.x;
    const int lane = t & 31, w = t >> 5;
    const int gi = (chunk << 8) + t;

    const unsigned int K = monokey(scores[(b << 11) + gi]);
    sk[t] = K;
    ctr[t] = 0;
    __syncthreads();

    // strict-less count: 64 x LDS.128 + 256 x (ISETP+IADD), 4 accumulators
    int r0 = 0, r1 = 0, r2 = 0, r3 = 0;
    const uint4* s4 = (const uint4*)sk;
    #pragma unroll 16
    for (int j = 0; j < 64; j++) {
        uint4 v = s4[j];
        r0 += (v.x < K);
        r1 += (v.y < K);
        r2 += (v.z < K);
        r3 += (v.w < K);
    }
    const int r = (r0 + r1) + (r2 + r3);

    // tie-safe scatter: tied elements share r; atomic hands out distinct slots
    const int off = atomicAdd(&ctr[r], 1);
    ssort[r + off] = K;
    __syncthreads();

    const unsigned int Ks = ssort[t];
    const float v = unmono(Ks);

    // inclusive block scan of sorted values
    float x = v;
    #pragma unroll
    for (int o = 1; o < 32; o <<= 1) {
        float y = __shfl_up_sync(0xffffffffu, x, o);
        if (lane >= o) x += y;
    }
    if (lane == 31) wtot[w] = x;
    __syncthreads();
    float offs = 0.f;
    #pragma unroll
    for (int ww = 0; ww < 7; ww++) if (ww < w) offs += wtot[ww];

    g_key[(b << 11) + gi]  = Ks;
    g_pref[(b << 11) + gi] = offs + x;
}

// ---------------------------------------------------------------------------
// Kernel B: per-element rank + smaller-sum via 8 interleaved branchless
// lower-bound searches over the sorted chunks staged in smem.
// B_i = s_i*(2r-n) + T - 2P. The upper-bound (tie-extent) search runs ONLY
// for elements near the top boundary (r >= 1776), so its cost is negligible;
// rank range [r, ru) fills the top-256 slots (ties write identical data).
// ---------------------------------------------------------------------------
__global__ __launch_bounds__(256) void bsum_search_kernel(const float* __restrict__ scores) {
    __shared__ __align__(16) unsigned int skey[DIM];   // 8 KB
    __shared__ __align__(16) float spref[DIM];         // 8 KB
    const int ic = blockIdx.x, b = blockIdx.y, t = threadIdx.x;

    {   // stage the whole row's sorted chunks
        const uint4* gk4 = (const uint4*)(g_key + (b << 11));
        uint4* sk4 = (uint4*)skey;
        #pragma unroll
        for (int c = 0; c < 2; c++) sk4[t + c * 256] = gk4[t + c * 256];
        const float4* gp4 = (const float4*)(g_pref + (b << 11));
        float4* sp4 = (float4*)spref;
        #pragma unroll
        for (int c = 0; c < 2; c++) sp4[t + c * 256] = gp4[t + c * 256];
    }
    __syncthreads();

    const int i = (ic << 8) + t;
    const float s = scores[(b << 11) + i];
    const unsigned int K = monokey(s);

    // 8 interleaved branchless lower-bound searches
    int pl[8];
    #pragma unroll
    for (int c = 0; c < 8; c++) pl[c] = 0;
    #pragma unroll
    for (int st = 128; st >= 1; st >>= 1) {
        #pragma unroll
        for (int c = 0; c < 8; c++)
            if (skey[(c << 8) + pl[c] + st - 1] < K) pl[c] += st;
    }
    #pragma unroll
    for (int c = 0; c < 8; c++)
        if (skey[(c << 8) + pl[c]] < K) pl[c]++;     // pl in [0,256]

    int r = 0;
    float P = 0.f, T = 0.f;
    #pragma unroll
    for (int c = 0; c < 8; c++) {
        r += pl[c];
        if (pl[c] > 0) P += spref[(c << 8) + pl[c] - 1];
        T += spref[(c << 8) + 255];
    }

    const float B = fmaf(s, (float)(2 * r - DIM), T - 2.f * P);
    g_bsum[(b << 11) + i] = B * LOG2E;

    // top-256 fill: only elements near the boundary need the tie extent
    if (r >= DIM - KTOP - 16) {
        const unsigned int Ku = K + 1;               // upper = lower_bound(K+1)
        int pu[8];
        #pragma unroll
        for (int c = 0; c < 8; c++) pu[c] = 0;
        #pragma unroll
        for (int st = 128; st >= 1; st >>= 1) {
            #pragma unroll
            for (int c = 0; c < 8; c++)
                if (skey[(c << 8) + pu[c] + st - 1] < Ku) pu[c] += st;
        }
        int ru = 0;
        #pragma unroll
        for (int c = 0; c < 8; c++) {
            if (skey[(c << 8) + pu[c]] < Ku) pu[c]++;
            ru += pu[c];
        }
        if (ru > DIM - KTOP) {
            int lo = r > (DIM - KTOP) ? r : (DIM - KTOP);
            for (int rr = lo; rr < ru; rr++) {       // almost always 1 iter
                g_topv[(b << 8) + rr - (DIM - KTOP)] = s * LOG2E;
                g_topB[(b << 8) + rr - (DIM - KTOP)] = B * LOG2E;
            }
        }
    }
}

// ---------------------------------------------------------------------------
// Kernel C: fused softmax writer (R8 config), k's processed in PAIRS. M is
// analytic (rank 2047-k element => slot 255-k): one barrier per 2 k's,
// double-buffered reduction slots. Grid (32 kg, 32 b) x 256 threads.
// ---------------------------------------------------------------------------
__global__ __launch_bounds__(256) void softmax_kernel(const float* __restrict__ scores,
                                                      float* __restrict__ out) {
    __shared__ float redS[32];                 // 2 buffers x (8+8) warp sums
    const int kg = blockIdx.x, b = blockIdx.y, t = threadIdx.x;
    const int lane = t & 31, w = t >> 5;

    const float4* sc4 = (const float4*)(scores + (b << 11));
    const float4* bs4 = (const float4*)(g_bsum + (b << 11));
    float4 a0 = sc4[t], a1 = sc4[t + 256];
    const float4 c0 = bs4[t], c1 = bs4[t + 256];
    a0.x *= LOG2E; a0.y *= LOG2E; a0.z *= LOG2E; a0.w *= LOG2E;
    a1.x *= LOG2E; a1.y *= LOG2E; a1.z *= LOG2E; a1.w *= LOG2E;

    #pragma unroll
    for (int kp = 0; kp < 4; kp++) {
        const int k0 = (kg << 3) + 2 * kp;
        const int k1 = k0 + 1;
        const float scal0 = (float)(DIM - 1 - 2 * k0);
        const float scal1 = (float)(DIM - 1 - 2 * k1);
        const float M0 = fmaf(scal0, __ldg(&g_topv[(b << 8) + 255 - k0]),
                              -__ldg(&g_topB[(b << 8) + 255 - k0]));
        const float M1 = fmaf(scal1, __ldg(&g_topv[(b << 8) + 255 - k1]),
                              -__ldg(&g_topB[(b << 8) + 255 - k1]));

        float e0[8], e1[8];
        e0[0] = ex2f(fmaf(a0.x, scal0, -c0.x) - M0);
        e0[1] = ex2f(fmaf(a0.y, scal0, -c0.y) - M0);
        e0[2] = ex2f(fmaf(a0.z, scal0, -c0.z) - M0);
        e0[3] = ex2f(fmaf(a0.w, scal0, -c0.w) - M0);
        e0[4] = ex2f(fmaf(a1.x, scal0, -c1.x) - M0);
        e0[5] = ex2f(fmaf(a1.y, scal0, -c1.y) - M0);
        e0[6] = ex2f(fmaf(a1.z, scal0, -c1.z) - M0);
        e0[7] = ex2f(fmaf(a1.w, scal0, -c1.w) - M0);
        e1[0] = ex2f(fmaf(a0.x, scal1, -c0.x) - M1);
        e1[1] = ex2f(fmaf(a0.y, scal1, -c0.y) - M1);
        e1[2] = ex2f(fmaf(a0.z, scal1, -c0.z) - M1);
        e1[3] = ex2f(fmaf(a0.w, scal1, -c0.w) - M1);
        e1[4] = ex2f(fmaf(a1.x, scal1, -c1.x) - M1);
        e1[5] = ex2f(fmaf(a1.y, scal1, -c1.y) - M1);
        e1[6] = ex2f(fmaf(a1.z, scal1, -c1.z) - M1);
        e1[7] = ex2f(fmaf(a1.w, scal1, -c1.w) - M1);

        float s0 = ((e0[0] + e0[1]) + (e0[2] + e0[3])) + ((e0[4] + e0[5]) + (e0[6] + e0[7]));
        float s1 = ((e1[0] + e1[1]) + (e1[2] + e1[3])) + ((e1[4] + e1[5]) + (e1[6] + e1[7]));
        #pragma unroll
        for (int o = 16; o; o >>= 1) {       // two independent chains overlap
            s0 += __shfl_xor_sync(0xffffffffu, s0, o);
            s1 += __shfl_xor_sync(0xffffffffu, s1, o);
        }
        const int p = (kp & 1) << 4;
        if (lane == 0) { redS[p + w] = s0; redS[p + 8 + w] = s1; }
        __syncthreads();                     // one barrier per 2 k's
        float S0 = redS[p + (lane & 7)];
        float S1 = redS[p + 8 + (lane & 7)];
        #pragma unroll
        for (int o = 4; o; o >>= 1) {
            S0 += __shfl_xor_sync(0xffffffffu, S0, o);
            S1 += __shfl_xor_sync(0xffffffffu, S1, o);
        }

        const float i0 = rcpf(S0);
        const float i1 = rcpf(S1);
        float4* o0p = (float4*)(out + ((size_t)((b << 8) + k0) << 11));
        float4* o1p = (float4*)(out + ((size_t)((b << 8) + k1) << 11));
        o0p[t]       = make_float4(e0[0] * i0, e0[1] * i0, e0[2] * i0, e0[3] * i0);
        o0p[t + 256] = make_float4(e0[4] * i0, e0[5] * i0, e0[6] * i0, e0[7] * i0);
        o1p[t]       = make_float4(e1[0] * i1, e1[1] * i1, e1[2] * i1, e1[3] * i1);
        o1p[t + 256] = make_float4(e1[4] * i1, e1[5] * i1, e1[6] * i1, e1[7] * i1);
    }
}

extern "C" void kernel_launch(void* const* d_in, const int* in_sizes, int n_in,
                              void* d_out, int out_size) {
    const float* scores = (const float*)d_in[0];
    float* out = (float*)d_out;

    chunk_rank_kernel<<<dim3(DIM / 256, BATCH), 256>>>(scores);
    bsum_search_kernel<<<dim3(DIM / 256, BATCH), 256>>>(scores);
    softmax_kernel<<<dim3(KTOP / 8, BATCH), 256>>>(scores, out);
}

// round 12
// speedup vs baseline: 1.1870x; 1.0083x over previous
#include <cuda_runtime.h>
#include <cuda_bf16.h>

#define DIM    2048
#define BATCH  32
#define KTOP   256
#define LOG2E  1.44269504f
#define CHUNK  512

// sorted chunk keys (monotonic u32, value-only) [b][chunk][512]
__device__ __align__(16) unsigned int g_key[BATCH * DIM];
// inclusive prefix sums of values in chunk-sorted order, same layout
__device__ __align__(16) float g_pref[BATCH * DIM];
// Bsum * log2e, original index order
__device__ __align__(16) float g_bsum[BATCH * DIM];
// top-256 by global rank: slot r-1792 holds (s*log2e, B*log2e) of rank-r element
__device__ __align__(16) float g_topv[BATCH * KTOP];
__device__ __align__(16) float g_topB[BATCH * KTOP];

__device__ __forceinline__ float ex2f(float x) {
    float r; asm("ex2.approx.ftz.f32 %0, %1;" : "=f"(r) : "f"(x)); return r;
}
__device__ __forceinline__ float rcpf(float x) {
    float r; asm("rcp.approx.f32 %0, %1;" : "=f"(r) : "f"(x)); return r;
}
__device__ __forceinline__ unsigned int monokey(float f) {
    unsigned int u = __float_as_uint(f);
    return u ^ (((unsigned int)((int)u >> 31)) | 0x80000000u);
}
__device__ __forceinline__ float unmono(unsigned int u) {
    return __uint_as_float(u ^ ((~((unsigned int)((int)u >> 31))) | 0x80000000u));
}

// ---------------------------------------------------------------------------
// Kernel A: chunk sort by rank counting, chunk=512. Grid (4, 32) = 128 blocks
// x 512 threads — exactly ONE wave on 148 SMs, 16 warps/block for latency
// cover. Each thread counts strict-less among its 512-chunk (vectorized
// LDS.128, 4 accumulator chains), resolves ties via smem atomic slot
// handout (tied elements carry equal values => deterministic), scatters to
// sorted order, then computes inclusive value-prefix sums.
// ---------------------------------------------------------------------------
__global__ __launch_bounds__(512) void chunk_rank_kernel(const float* __restrict__ scores) {
    __shared__ __align__(16) unsigned int sk[CHUNK];
    __shared__ unsigned int ssort[CHUNK];
    __shared__ int ctr[CHUNK];
    __shared__ float wtot[16];
    const int chunk = blockIdx.x, b = blockIdx.y, t = threadIdx.x;
    const int lane = t & 31, w = t >> 5;
    const int gi = (chunk << 9) + t;

    const unsigned int K = monokey(scores[(b << 11) + gi]);
    sk[t] = K;
    ctr[t] = 0;
    __syncthreads();

    // strict-less count: 128 x LDS.128 + 512 x (ISETP+IADD), 4 chains
    int r0 = 0, r1 = 0, r2 = 0, r3 = 0;
    const uint4* s4 = (const uint4*)sk;
    #pragma unroll 16
    for (int j = 0; j < CHUNK / 4; j++) {
        uint4 v = s4[j];
        r0 += (v.x < K);
        r1 += (v.y < K);
        r2 += (v.z < K);
        r3 += (v.w < K);
    }
    const int r = (r0 + r1) + (r2 + r3);

    // tie-safe scatter: tied elements share r; atomic hands out distinct slots
    const int off = atomicAdd(&ctr[r], 1);
    ssort[r + off] = K;
    __syncthreads();

    const unsigned int Ks = ssort[t];
    const float v = unmono(Ks);

    // inclusive block scan of sorted values (16 warps)
    float x = v;
    #pragma unroll
    for (int o = 1; o < 32; o <<= 1) {
        float y = __shfl_up_sync(0xffffffffu, x, o);
        if (lane >= o) x += y;
    }
    if (lane == 31) wtot[w] = x;
    __syncthreads();
    float offs = 0.f;
    #pragma unroll
    for (int ww = 0; ww < 15; ww++) if (ww < w) offs += wtot[ww];

    g_key[(b << 11) + gi]  = Ks;
    g_pref[(b << 11) + gi] = offs + x;
}

// ---------------------------------------------------------------------------
// Kernel B: per-element rank + smaller-sum via 4 interleaved branchless
// lower-bound searches (10 probes each) over the 4 sorted 512-chunks staged
// in smem. Grid (4, 32) = 128 blocks x 512 threads — one wave.
// B_i = s_i*(2r-n) + T - 2P. Upper-bound (tie-extent) search runs only for
// elements near the top boundary; rank range [r, ru) fills the top-256 slots
// (ties write identical data).
// ---------------------------------------------------------------------------
__global__ __launch_bounds__(512) void bsum_search_kernel(const float* __restrict__ scores) {
    __shared__ __align__(16) unsigned int skey[DIM];   // 8 KB
    __shared__ __align__(16) float spref[DIM];         // 8 KB
    const int ic = blockIdx.x, b = blockIdx.y, t = threadIdx.x;

    {   // stage the whole row's sorted chunks (512 threads x 1 uint4/float4)
        ((uint4*)skey)[t]  = ((const uint4*)(g_key  + (b << 11)))[t];
        ((float4*)spref)[t] = ((const float4*)(g_pref + (b << 11)))[t];
    }
    __syncthreads();

    const int i = (ic << 9) + t;
    const float s = scores[(b << 11) + i];
    const unsigned int K = monokey(s);

    // 4 interleaved branchless lower-bound searches over 512-entry chunks
    int pl[4];
    #pragma unroll
    for (int c = 0; c < 4; c++) pl[c] = 0;
    #pragma unroll
    for (int st = 256; st >= 1; st >>= 1) {
        #pragma unroll
        for (int c = 0; c < 4; c++)
            if (skey[(c << 9) + pl[c] + st - 1] < K) pl[c] += st;
    }
    #pragma unroll
    for (int c = 0; c < 4; c++)
        if (skey[(c << 9) + pl[c]] < K) pl[c]++;     // pl in [0,512]

    int r = 0;
    float P = 0.f, T = 0.f;
    #pragma unroll
    for (int c = 0; c < 4; c++) {
        r += pl[c];
        if (pl[c] > 0) P += spref[(c << 9) + pl[c] - 1];
        T += spref[(c << 9) + 511];
    }

    const float B = fmaf(s, (float)(2 * r - DIM), T - 2.f * P);
    g_bsum[(b << 11) + i] = B * LOG2E;

    // top-256 fill: only elements near the boundary need the tie extent
    if (r >= DIM - KTOP - 16) {
        const unsigned int Ku = K + 1;               // upper = lower_bound(K+1)
        int pu[4];
        #pragma unroll
        for (int c = 0; c < 4; c++) pu[c] = 0;
        #pragma unroll
        for (int st = 256; st >= 1; st >>= 1) {
            #pragma unroll
            for (int c = 0; c < 4; c++)
                if (skey[(c << 9) + pu[c] + st - 1] < Ku) pu[c] += st;
        }
        int ru = 0;
        #pragma unroll
        for (int c = 0; c < 4; c++) {
            if (skey[(c << 9) + pu[c]] < Ku) pu[c]++;
            ru += pu[c];
        }
        if (ru > DIM - KTOP) {
            int lo = r > (DIM - KTOP) ? r : (DIM - KTOP);
            for (int rr = lo; rr < ru; rr++) {       // almost always 1 iter
                g_topv[(b << 8) + rr - (DIM - KTOP)] = s * LOG2E;
                g_topB[(b << 8) + rr - (DIM - KTOP)] = B * LOG2E;
            }
        }
    }
}

// ---------------------------------------------------------------------------
// Kernel C: fused softmax writer (proven R8 config), k's processed in PAIRS.
// M is analytic (rank 2047-k element => slot 255-k): one barrier per 2 k's,
// double-buffered reduction slots. Grid (32 kg, 32 b) x 256 threads.
// ---------------------------------------------------------------------------
__global__ __launch_bounds__(256) void softmax_kernel(const float* __restrict__ scores,
                                                      float* __restrict__ out) {
    __shared__ float redS[32];                 // 2 buffers x (8+8) warp sums
    const int kg = blockIdx.x, b = blockIdx.y, t = threadIdx.x;
    const int lane = t & 31, w = t >> 5;

    const float4* sc4 = (const float4*)(scores + (b << 11));
    const float4* bs4 = (const float4*)(g_bsum + (b << 11));
    float4 a0 = sc4[t], a1 = sc4[t + 256];
    const float4 c0 = bs4[t], c1 = bs4[t + 256];
    a0.x *= LOG2E; a0.y *= LOG2E; a0.z *= LOG2E; a0.w *= LOG2E;
    a1.x *= LOG2E; a1.y *= LOG2E; a1.z *= LOG2E; a1.w *= LOG2E;

    #pragma unroll
    for (int kp = 0; kp < 4; kp++) {
        const int k0 = (kg << 3) + 2 * kp;
        const int k1 = k0 + 1;
        const float scal0 = (float)(DIM - 1 - 2 * k0);
        const float scal1 = (float)(DIM - 1 - 2 * k1);
        const float M0 = fmaf(scal0, __ldg(&g_topv[(b << 8) + 255 - k0]),
                              -__ldg(&g_topB[(b << 8) + 255 - k0]));
        const float M1 = fmaf(scal1, __ldg(&g_topv[(b << 8) + 255 - k1]),
                              -__ldg(&g_topB[(b << 8) + 255 - k1]));

        float e0[8], e1[8];
        e0[0] = ex2f(fmaf(a0.x, scal0, -c0.x) - M0);
        e0[1] = ex2f(fmaf(a0.y, scal0, -c0.y) - M0);
        e0[2] = ex2f(fmaf(a0.z, scal0, -c0.z) - M0);
        e0[3] = ex2f(fmaf(a0.w, scal0, -c0.w) - M0);
        e0[4] = ex2f(fmaf(a1.x, scal0, -c1.x) - M0);
        e0[5] = ex2f(fmaf(a1.y, scal0, -c1.y) - M0);
        e0[6] = ex2f(fmaf(a1.z, scal0, -c1.z) - M0);
        e0[7] = ex2f(fmaf(a1.w, scal0, -c1.w) - M0);
        e1[0] = ex2f(fmaf(a0.x, scal1, -c0.x) - M1);
        e1[1] = ex2f(fmaf(a0.y, scal1, -c0.y) - M1);
        e1[2] = ex2f(fmaf(a0.z, scal1, -c0.z) - M1);
        e1[3] = ex2f(fmaf(a0.w, scal1, -c0.w) - M1);
        e1[4] = ex2f(fmaf(a1.x, scal1, -c1.x) - M1);
        e1[5] = ex2f(fmaf(a1.y, scal1, -c1.y) - M1);
        e1[6] = ex2f(fmaf(a1.z, scal1, -c1.z) - M1);
        e1[7] = ex2f(fmaf(a1.w, scal1, -c1.w) - M1);

        float s0 = ((e0[0] + e0[1]) + (e0[2] + e0[3])) + ((e0[4] + e0[5]) + (e0[6] + e0[7]));
        float s1 = ((e1[0] + e1[1]) + (e1[2] + e1[3])) + ((e1[4] + e1[5]) + (e1[6] + e1[7]));
        #pragma unroll
        for (int o = 16; o; o >>= 1) {       // two independent chains overlap
            s0 += __shfl_xor_sync(0xffffffffu, s0, o);
            s1 += __shfl_xor_sync(0xffffffffu, s1, o);
        }
        const int p = (kp & 1) << 4;
        if (lane == 0) { redS[p + w] = s0; redS[p + 8 + w] = s1; }
        __syncthreads();                     // one barrier per 2 k's
        float S0 = redS[p + (lane & 7)];
        float S1 = redS[p + 8 + (lane & 7)];
        #pragma unroll
        for (int o = 4; o; o >>= 1) {
            S0 += __shfl_xor_sync(0xffffffffu, S0, o);
            S1 += __shfl_xor_sync(0xffffffffu, S1, o);
        }

        const float i0 = rcpf(S0);
        const float i1 = rcpf(S1);
        float4* o0p = (float4*)(out + ((size_t)((b << 8) + k0) << 11));
        float4* o1p = (float4*)(out + ((size_t)((b << 8) + k1) << 11));
        o0p[t]       = make_float4(e0[0] * i0, e0[1] * i0, e0[2] * i0, e0[3] * i0);
        o0p[t + 256] = make_float4(e0[4] * i0, e0[5] * i0, e0[6] * i0, e0[7] * i0);
        o1p[t]       = make_float4(e1[0] * i1, e1[1] * i1, e1[2] * i1, e1[3] * i1);
        o1p[t + 256] = make_float4(e1[4] * i1, e1[5] * i1, e1[6] * i1, e1[7] * i1);
    }
}

extern "C" void kernel_launch(void* const* d_in, const int* in_sizes, int n_in,
                              void* d_out, int out_size) {
    const float* scores = (const float*)d_in[0];
    float* out = (float*)d_out;

    chunk_rank_kernel<<<dim3(DIM / CHUNK, BATCH), CHUNK>>>(scores);
    bsum_search_kernel<<<dim3(DIM / CHUNK, BATCH), CHUNK>>>(scores);
    softmax_kernel<<<dim3(KTOP / 8, BATCH), 256>>>(scores, out);
}